// round 4
// baseline (speedup 1.0000x reference)
#include <cuda_runtime.h>

// ForceAggregation: out[m*D + r] = dot(hess[m][r][:], ns[m][:]),  D=300, M=2048.
// hess = 737 MB streamed once; binding resource is L2/LTS bandwidth.
// Key insight: ns re-reads through L2 were stealing 12-25% of LTS bandwidth.
// -> block per molecule: ns staged to SMEM once (0.3% overhead), warp copies its
//    3 ns chunks to registers once, then loops over row-quads with
//    12 front-batched LDG.128.LDCS per iteration (MLP=12).

#define BLOCK_THREADS 256
#define WARPS_PER_BLOCK (BLOCK_THREADS / 32)

__device__ __forceinline__ float dot4(float4 a, float4 b, float acc) {
    acc = fmaf(a.x, b.x, acc);
    acc = fmaf(a.y, b.y, acc);
    acc = fmaf(a.z, b.z, acc);
    return fmaf(a.w, b.w, acc);
}

__global__ void __launch_bounds__(BLOCK_THREADS)
force_agg_300(const float* __restrict__ hess,
              const float* __restrict__ ns,
              float* __restrict__ out)
{
    constexpr int D   = 300;
    constexpr int NCH = D / 4;     // 75 float4 chunks per row
    constexpr int QPM = D / 4;     // 75 row-quads per molecule

    __shared__ __align__(16) float s_ns[D];

    const int m    = blockIdx.x;
    const int warp = threadIdx.x >> 5;
    const int lane = threadIdx.x & 31;

    // Stage ns_m into SMEM once per molecule (single pass: 75 float4 < 256 thr).
    if (threadIdx.x < NCH)
        ((float4*)s_ns)[threadIdx.x] = __ldg((const float4*)(ns + (size_t)m * D) + threadIdx.x);
    __syncthreads();

    // Copy this lane's 3 ns chunks SMEM -> registers ONCE; reused for all quads.
    const float4 z4 = make_float4(0.f, 0.f, 0.f, 0.f);
    const float4* s4 = (const float4*)s_ns;
    const float4 n0 = s4[lane];
    const float4 n1 = s4[lane + 32];
    const float4 n2 = (lane < NCH - 64) ? s4[lane + 64] : z4;

    const float* hmol = hess + (size_t)m * D * D;
    float*       omol = out + (size_t)m * D;

    // Warp handles quads warp, warp+8, ... (75 quads: warps 0-2 get 10, 3-7 get 9)
    for (int quad = warp; quad < QPM; quad += WARPS_PER_BLOCK) {
        const int r = quad << 2;
        const float* hbase = hmol + (size_t)r * D;
        const float4* h0 = (const float4*)(hbase);
        const float4* h1 = (const float4*)(hbase + D);
        const float4* h2 = (const float4*)(hbase + 2 * D);
        const float4* h3 = (const float4*)(hbase + 3 * D);

        // Front-batch 12 independent streaming loads (evict-first).
        float4 a0 = __ldcs(h0 + lane);
        float4 b0 = __ldcs(h1 + lane);
        float4 c0 = __ldcs(h2 + lane);
        float4 d0 = __ldcs(h3 + lane);
        float4 a1 = __ldcs(h0 + lane + 32);
        float4 b1 = __ldcs(h1 + lane + 32);
        float4 c1 = __ldcs(h2 + lane + 32);
        float4 d1 = __ldcs(h3 + lane + 32);
        float4 a2 = z4, b2 = z4, c2 = z4, d2 = z4;
        if (lane < NCH - 64) {
            a2 = __ldcs(h0 + lane + 64);
            b2 = __ldcs(h1 + lane + 64);
            c2 = __ldcs(h2 + lane + 64);
            d2 = __ldcs(h3 + lane + 64);
        }

        float acc0 = dot4(a0, n0, 0.f);
        float acc1 = dot4(b0, n0, 0.f);
        float acc2 = dot4(c0, n0, 0.f);
        float acc3 = dot4(d0, n0, 0.f);
        acc0 = dot4(a1, n1, acc0);
        acc1 = dot4(b1, n1, acc1);
        acc2 = dot4(c1, n1, acc2);
        acc3 = dot4(d1, n1, acc3);
        acc0 = dot4(a2, n2, acc0);
        acc1 = dot4(b2, n2, acc1);
        acc2 = dot4(c2, n2, acc2);
        acc3 = dot4(d2, n2, acc3);

        // Interleaved select-butterfly: 9 shuffles reduce all 4 accumulators.
        acc0 += __shfl_xor_sync(0xffffffffu, acc0, 16);
        acc1 += __shfl_xor_sync(0xffffffffu, acc1, 16);
        acc2 += __shfl_xor_sync(0xffffffffu, acc2, 16);
        acc3 += __shfl_xor_sync(0xffffffffu, acc3, 16);
        float v0 = (lane & 16) ? acc1 : acc0;
        float v1 = (lane & 16) ? acc3 : acc2;
        v0 += __shfl_xor_sync(0xffffffffu, v0, 8);
        v1 += __shfl_xor_sync(0xffffffffu, v1, 8);
        float w = (lane & 8) ? v1 : v0;
        w += __shfl_xor_sync(0xffffffffu, w, 4);
        w += __shfl_xor_sync(0xffffffffu, w, 2);
        w += __shfl_xor_sync(0xffffffffu, w, 1);

        if ((lane & 7) == 0) {
            // lane 0 -> r, lane 8 -> r+2, lane 16 -> r+1, lane 24 -> r+3
            const int rowoff = (((lane >> 3) & 1) << 1) | (lane >> 4);
            omol[r + rowoff] = w;
        }
    }
}

// Generic fallback for unexpected D (runtime loop bounds, smem-staged ns).
__global__ void __launch_bounds__(BLOCK_THREADS)
force_agg_generic(const float* __restrict__ hess,
                  const float* __restrict__ ns,
                  float* __restrict__ out,
                  int D)
{
    extern __shared__ __align__(16) float s_ns[];

    const int m = blockIdx.x;
    const float* nsm = ns + (size_t)m * D;
    const int nch = D >> 2;
    for (int i = threadIdx.x; i < nch; i += BLOCK_THREADS)
        ((float4*)s_ns)[i] = ((const float4*)nsm)[i];
    for (int i = nch * 4 + threadIdx.x; i < D; i += BLOCK_THREADS)
        s_ns[i] = nsm[i];
    __syncthreads();

    const int warp  = threadIdx.x >> 5;
    const int lane  = threadIdx.x & 31;

    const float4* s4    = (const float4*)s_ns;
    const float*  hbase = hess + (size_t)m * D * D;

    for (int r = warp; r < D; r += WARPS_PER_BLOCK) {
        const float4* hrow = (const float4*)(hbase + (size_t)r * D);
        float acc = 0.0f;
        for (int c = lane; c < nch; c += 32) {
            const float4 h = __ldcs(hrow + c);
            const float4 n = s4[c];
            acc = fmaf(h.x, n.x, acc);
            acc = fmaf(h.y, n.y, acc);
            acc = fmaf(h.z, n.z, acc);
            acc = fmaf(h.w, n.w, acc);
        }
        for (int c = nch * 4 + lane; c < D; c += 32)
            acc = fmaf(hbase[(size_t)r * D + c], s_ns[c], acc);
#pragma unroll
        for (int off = 16; off; off >>= 1)
            acc += __shfl_xor_sync(0xffffffffu, acc, off);
        if (lane == 0)
            out[(size_t)m * D + r] = acc;
    }
}

extern "C" void kernel_launch(void* const* d_in, const int* in_sizes, int n_in,
                              void* d_out, int out_size)
{
    // Input order: ns [M*N_AT,3] f32, hess [M*D,D] f32, idx_m i32, n_atoms [M] i32
    const float* ns   = (const float*)d_in[0];
    const float* hess = (const float*)d_in[1];
    float*       out  = (float*)d_out;

    const int M = in_sizes[3];
    const int D = (int)((long long)in_sizes[0] / M);

    if (D == 300) {
        force_agg_300<<<M, BLOCK_THREADS>>>(hess, ns, out);
    } else {
        const size_t shmem = (size_t)((D + 3) / 4) * 16;
        force_agg_generic<<<M, BLOCK_THREADS, shmem>>>(hess, ns, out, D);
    }
}

// round 5
// speedup vs baseline: 1.1005x; 1.1005x over previous
#include <cuda_runtime.h>
#include <cstdint>

// ForceAggregation: out[m*D + r] = dot(hess[m][r][:], ns[m][:]),  D=300, M=2048.
// hess = 737 MB streamed once. This version replaces per-warp scattered LDGs with
// cp.async.bulk contiguous 19.2KB stage copies into a 5-deep SMEM ring:
//  - DRAM sees long sequential bursts (HBM row-buffer hits) instead of ~5000
//    interleaved 1.2KB row streams
//  - the ring keeps ~190KB/SM in flight continuously, decoupling load issue
//    from the compute/reduce dead windows

#define BLOCK_THREADS 256

// ---------------- PTX helpers (minimal, self-contained) ----------------
__device__ __forceinline__ uint32_t smem_u32(const void* p) {
    uint32_t a;
    asm("{ .reg .u64 t; cvta.to.shared.u64 t, %1; cvt.u32.u64 %0, t; }"
        : "=r"(a) : "l"(p));
    return a;
}
__device__ __forceinline__ void mbar_init(uint32_t mbar, uint32_t count) {
    asm volatile("mbarrier.init.shared.b64 [%0], %1;" :: "r"(mbar), "r"(count) : "memory");
}
__device__ __forceinline__ void mbar_expect_tx(uint32_t mbar, uint32_t bytes) {
    asm volatile("mbarrier.arrive.expect_tx.shared.b64 _, [%0], %1;"
                 :: "r"(mbar), "r"(bytes) : "memory");
}
__device__ __forceinline__ void mbar_wait(uint32_t mbar, uint32_t parity) {
    uint32_t done;
    asm volatile(
        "{\n\t.reg .pred p;\n\t"
        "mbarrier.try_wait.parity.acquire.cta.shared::cta.b64 p, [%1], %2;\n\t"
        "selp.b32 %0, 1, 0, p;\n\t}"
        : "=r"(done) : "r"(mbar), "r"(parity) : "memory");
    if (!done) {
        asm volatile(
            "{\n\t.reg .pred P1;\n\t"
            "WAIT_LOOP_%=:\n\t"
            "mbarrier.try_wait.parity.acquire.cta.shared::cta.b64 P1, [%0], %1, 0x989680;\n\t"
            "@P1 bra.uni WAIT_DONE_%=;\n\t"
            "bra.uni WAIT_LOOP_%=;\n\t"
            "WAIT_DONE_%=:\n\t}"
            :: "r"(mbar), "r"(parity) : "memory");
    }
}
__device__ __forceinline__ void bulk_copy_g2s(uint32_t dst_smem, const void* src_gmem,
                                              uint32_t bytes, uint32_t mbar) {
    asm volatile(
        "cp.async.bulk.shared::cta.global.mbarrier::complete_tx::bytes [%0], [%1], %2, [%3];"
        :: "r"(dst_smem), "l"(src_gmem), "r"(bytes), "r"(mbar) : "memory");
}
__device__ __forceinline__ void fence_proxy_async_cta() {
    asm volatile("fence.proxy.async.shared::cta;" ::: "memory");
}
// -----------------------------------------------------------------------

#define D300        300
#define ROWS_STAGE  16
#define NSTAGES     5
#define STAGE_FLTS  (ROWS_STAGE * D300)       // 4800 floats
#define STAGE_BYTES (STAGE_FLTS * 4)          // 19200 B
#define NTILES      ((D300 + ROWS_STAGE - 1) / ROWS_STAGE)   // 19 (last tile = 12 rows)
#define SMEM_DYN    (NSTAGES * STAGE_BYTES)   // 96000 B

__global__ void __launch_bounds__(BLOCK_THREADS)
force_agg_300_tma(const float* __restrict__ hess,
                  const float* __restrict__ ns,
                  float* __restrict__ out)
{
    extern __shared__ __align__(16) float ring[];     // [NSTAGES][ROWS_STAGE][300]
    __shared__ __align__(16) float s_ns[D300];
    __shared__ __align__(8) uint64_t full_bar[NSTAGES];

    const int m    = blockIdx.x;
    const int tid  = threadIdx.x;
    const int warp = tid >> 5;
    const int lane = tid & 31;

    // Stage ns_m into SMEM (75 float4 loads, threads 0..74).
    if (tid < D300 / 4)
        ((float4*)s_ns)[tid] = __ldg((const float4*)(ns + (size_t)m * D300) + tid);

    // Init barriers.
    if (tid == 0) {
#pragma unroll
        for (int s = 0; s < NSTAGES; ++s)
            mbar_init(smem_u32(&full_bar[s]), 1);
    }
    __syncthreads();

    const float* hmol = hess + (size_t)m * D300 * D300;
    float*       omol = out + (size_t)m * D300;

    // Prefill ring.
    if (tid == 0) {
#pragma unroll
        for (int t = 0; t < NSTAGES; ++t) {
            const uint32_t bytes = (t == NTILES - 1)
                ? (uint32_t)((D300 - t * ROWS_STAGE) * D300 * 4) : (uint32_t)STAGE_BYTES;
            const uint32_t mb = smem_u32(&full_bar[t]);
            mbar_expect_tx(mb, bytes);
            bulk_copy_g2s(smem_u32(ring) + t * STAGE_BYTES,
                          hmol + (size_t)t * STAGE_FLTS, bytes, mb);
        }
    }

    // ns chunks for this lane, reused for every row.
    const float4 z4 = make_float4(0.f, 0.f, 0.f, 0.f);
    const float4* s4 = (const float4*)s_ns;
    const float4 n0 = s4[lane];
    const float4 n1 = s4[lane + 32];
    const float4 n2 = (lane < (D300 / 4) - 64) ? s4[lane + 64] : z4;

    for (int t = 0; t < NTILES; ++t) {
        const int s = t % NSTAGES;
        const uint32_t parity = (uint32_t)((t / NSTAGES) & 1);
        mbar_wait(smem_u32(&full_bar[s]), parity);

        const int r0    = t * ROWS_STAGE;
        const int nrows = (t == NTILES - 1) ? (D300 - r0) : ROWS_STAGE;

        const float* stg = ring + (size_t)s * STAGE_FLTS;
        const int rowA = warp;                 // always < nrows (nrows >= 12 > 7)
        const int rowB = warp + 8;
        const bool hasB = (rowB < nrows);

        const float4* pA = (const float4*)(stg + rowA * D300);
        const float4* pB = (const float4*)(stg + rowB * D300);   // in-bounds SMEM even if stale

        float accA, accB;
        {
            float4 a0 = pA[lane],      b0 = pB[lane];
            float4 a1 = pA[lane + 32], b1 = pB[lane + 32];
            float4 a2 = z4, b2 = z4;
            if (lane < (D300 / 4) - 64) { a2 = pA[lane + 64]; b2 = pB[lane + 64]; }

            accA = fmaf(a0.x, n0.x, 0.f);  accB = fmaf(b0.x, n0.x, 0.f);
            accA = fmaf(a0.y, n0.y, accA); accB = fmaf(b0.y, n0.y, accB);
            accA = fmaf(a0.z, n0.z, accA); accB = fmaf(b0.z, n0.z, accB);
            accA = fmaf(a0.w, n0.w, accA); accB = fmaf(b0.w, n0.w, accB);
            accA = fmaf(a1.x, n1.x, accA); accB = fmaf(b1.x, n1.x, accB);
            accA = fmaf(a1.y, n1.y, accA); accB = fmaf(b1.y, n1.y, accB);
            accA = fmaf(a1.z, n1.z, accA); accB = fmaf(b1.z, n1.z, accB);
            accA = fmaf(a1.w, n1.w, accA); accB = fmaf(b1.w, n1.w, accB);
            accA = fmaf(a2.x, n2.x, accA); accB = fmaf(b2.x, n2.x, accB);
            accA = fmaf(a2.y, n2.y, accA); accB = fmaf(b2.y, n2.y, accB);
            accA = fmaf(a2.z, n2.z, accA); accB = fmaf(b2.z, n2.z, accB);
            accA = fmaf(a2.w, n2.w, accA); accB = fmaf(b2.w, n2.w, accB);
        }

        // Paired 6-shuffle reduction: lane0 -> rowA, lane16 -> rowB.
        accA += __shfl_xor_sync(0xffffffffu, accA, 16);
        accB += __shfl_xor_sync(0xffffffffu, accB, 16);
        float v = (lane & 16) ? accB : accA;
        v += __shfl_xor_sync(0xffffffffu, v, 8);
        v += __shfl_xor_sync(0xffffffffu, v, 4);
        v += __shfl_xor_sync(0xffffffffu, v, 2);
        v += __shfl_xor_sync(0xffffffffu, v, 1);
        if (lane == 0)               omol[r0 + rowA] = v;
        else if (lane == 16 && hasB) omol[r0 + rowB] = v;

        // All warps done reading stage s -> refill it with tile t+NSTAGES.
        __syncthreads();
        if (tid == 0 && t + NSTAGES < NTILES) {
            const int tn = t + NSTAGES;
            const uint32_t bytes = (tn == NTILES - 1)
                ? (uint32_t)((D300 - tn * ROWS_STAGE) * D300 * 4) : (uint32_t)STAGE_BYTES;
            const uint32_t mb = smem_u32(&full_bar[s]);
            fence_proxy_async_cta();
            mbar_expect_tx(mb, bytes);
            bulk_copy_g2s(smem_u32(ring) + s * STAGE_BYTES,
                          hmol + (size_t)tn * STAGE_FLTS, bytes, mb);
        }
    }
}

// Generic fallback for unexpected D (runtime loop bounds, smem-staged ns).
__global__ void __launch_bounds__(BLOCK_THREADS)
force_agg_generic(const float* __restrict__ hess,
                  const float* __restrict__ ns,
                  float* __restrict__ out,
                  int D)
{
    extern __shared__ __align__(16) float s_ns[];

    const int m = blockIdx.x;
    const float* nsm = ns + (size_t)m * D;
    const int nch = D >> 2;
    for (int i = threadIdx.x; i < nch; i += BLOCK_THREADS)
        ((float4*)s_ns)[i] = ((const float4*)nsm)[i];
    for (int i = nch * 4 + threadIdx.x; i < D; i += BLOCK_THREADS)
        s_ns[i] = nsm[i];
    __syncthreads();

    const int warp = threadIdx.x >> 5;
    const int lane = threadIdx.x & 31;

    const float4* s4    = (const float4*)s_ns;
    const float*  hbase = hess + (size_t)m * D * D;

    for (int r = warp; r < D; r += BLOCK_THREADS / 32) {
        const float4* hrow = (const float4*)(hbase + (size_t)r * D);
        float acc = 0.0f;
        for (int c = lane; c < nch; c += 32) {
            const float4 h = __ldcs(hrow + c);
            const float4 n = s4[c];
            acc = fmaf(h.x, n.x, acc);
            acc = fmaf(h.y, n.y, acc);
            acc = fmaf(h.z, n.z, acc);
            acc = fmaf(h.w, n.w, acc);
        }
        for (int c = nch * 4 + lane; c < D; c += 32)
            acc = fmaf(hbase[(size_t)r * D + c], s_ns[c], acc);
#pragma unroll
        for (int off = 16; off; off >>= 1)
            acc += __shfl_xor_sync(0xffffffffu, acc, off);
        if (lane == 0)
            out[(size_t)m * D + r] = acc;
    }
}

extern "C" void kernel_launch(void* const* d_in, const int* in_sizes, int n_in,
                              void* d_out, int out_size)
{
    // Input order: ns [M*N_AT,3] f32, hess [M*D,D] f32, idx_m i32, n_atoms [M] i32
    const float* ns   = (const float*)d_in[0];
    const float* hess = (const float*)d_in[1];
    float*       out  = (float*)d_out;

    const int M = in_sizes[3];
    const int D = (int)((long long)in_sizes[0] / M);

    if (D == 300) {
        cudaFuncSetAttribute(force_agg_300_tma,
                             cudaFuncAttributeMaxDynamicSharedMemorySize, SMEM_DYN);
        force_agg_300_tma<<<M, BLOCK_THREADS, SMEM_DYN>>>(hess, ns, out);
    } else {
        const size_t shmem = (size_t)((D + 3) / 4) * 16;
        force_agg_generic<<<M, BLOCK_THREADS, shmem>>>(hess, ns, out, D);
    }
}

// round 6
// speedup vs baseline: 1.1678x; 1.0611x over previous
#include <cuda_runtime.h>

// ForceAggregation: out[m*D + r] = dot(hess[m][r][:], ns[m][:]),  D=300, M=2048.
// hess = 737 MB streamed once; DRAM request-supply gaps are the remaining loss.
// R2 structure (warp = row pair, 64-row tiles, grid 10240) + SOFTWARE PIPELINE:
// prefetch next pair's 6 LDG.128.LDCS before reducing current pair, so loads
// stay outstanding through the FMA/shuffle dead window. 6-shuffle paired reduce.

#define ROWS_PER_BLOCK 64
#define BLOCK_THREADS 256

__device__ __forceinline__ float dot4(float4 a, float4 b, float acc) {
    acc = fmaf(a.x, b.x, acc);
    acc = fmaf(a.y, b.y, acc);
    acc = fmaf(a.z, b.z, acc);
    return fmaf(a.w, b.w, acc);
}

__global__ void __launch_bounds__(BLOCK_THREADS)
force_agg_300(const float* __restrict__ hess,
              const float* __restrict__ ns,
              float* __restrict__ out,
              int tiles_per_mol)
{
    constexpr int D   = 300;
    constexpr int NCH = D / 4;          // 75 float4 chunks per row

    const int m    = blockIdx.x / tiles_per_mol;
    const int tile = blockIdx.x - m * tiles_per_mol;
    const int row0 = tile * ROWS_PER_BLOCK;

    const int warp = threadIdx.x >> 5;
    const int lane = threadIdx.x & 31;

    const float4 z4 = make_float4(0.f, 0.f, 0.f, 0.f);

    // ns chunks for this lane — reused by all rows this warp touches.
    const float4* ns4 = (const float4*)(ns + (size_t)m * D);
    const bool has2 = (lane < NCH - 64);
    float4 n0 = __ldg(ns4 + lane);
    float4 n1 = __ldg(ns4 + lane + 32);
    float4 n2 = has2 ? __ldg(ns4 + lane + 64) : z4;

    const float* hbase = hess + (size_t)m * D * D;

    int rend = row0 + ROWS_PER_BLOCK;
    if (rend > D) rend = D;            // rend - row0 always even (D even)

    int r = row0 + (warp << 1);
    if (r >= rend) return;

    // ---- prologue: load current pair ----
    const float4* h0 = (const float4*)(hbase + (size_t)r * D);
    const float4* h1 = (const float4*)(hbase + (size_t)(r + 1) * D);
    float4 a0 = __ldcs(h0 + lane);
    float4 b0 = __ldcs(h1 + lane);
    float4 a1 = __ldcs(h0 + lane + 32);
    float4 b1 = __ldcs(h1 + lane + 32);
    float4 a2 = z4, b2 = z4;
    if (has2) { a2 = __ldcs(h0 + lane + 64); b2 = __ldcs(h1 + lane + 64); }

    for (; r < rend; r += 16) {
        // ---- prefetch next pair (kept in flight during reduce) ----
        const int rn = r + 16;
        const bool more = (rn < rend);
        float4 pa0 = z4, pb0 = z4, pa1 = z4, pb1 = z4, pa2 = z4, pb2 = z4;
        if (more) {
            const float4* g0 = (const float4*)(hbase + (size_t)rn * D);
            const float4* g1 = (const float4*)(hbase + (size_t)(rn + 1) * D);
            pa0 = __ldcs(g0 + lane);
            pb0 = __ldcs(g1 + lane);
            pa1 = __ldcs(g0 + lane + 32);
            pb1 = __ldcs(g1 + lane + 32);
            if (has2) { pa2 = __ldcs(g0 + lane + 64); pb2 = __ldcs(g1 + lane + 64); }
        }

        // ---- compute current pair ----
        float acc0 = dot4(a0, n0, 0.f);
        float acc1 = dot4(b0, n0, 0.f);
        acc0 = dot4(a1, n1, acc0);
        acc1 = dot4(b1, n1, acc1);
        acc0 = dot4(a2, n2, acc0);
        acc1 = dot4(b2, n2, acc1);

        // ---- 6-shuffle paired reduction: lane0 -> r, lane16 -> r+1 ----
        acc0 += __shfl_xor_sync(0xffffffffu, acc0, 16);
        acc1 += __shfl_xor_sync(0xffffffffu, acc1, 16);
        float v = (lane & 16) ? acc1 : acc0;
        v += __shfl_xor_sync(0xffffffffu, v, 8);
        v += __shfl_xor_sync(0xffffffffu, v, 4);
        v += __shfl_xor_sync(0xffffffffu, v, 2);
        v += __shfl_xor_sync(0xffffffffu, v, 1);
        if (lane == 0)       out[(size_t)m * D + r]     = v;
        else if (lane == 16) out[(size_t)m * D + r + 1] = v;

        // ---- rotate pipeline ----
        a0 = pa0; b0 = pb0; a1 = pa1; b1 = pb1; a2 = pa2; b2 = pb2;
    }
}

// Generic fallback for unexpected D (runtime loop bounds, smem-staged ns).
__global__ void __launch_bounds__(BLOCK_THREADS)
force_agg_generic(const float* __restrict__ hess,
                  const float* __restrict__ ns,
                  float* __restrict__ out,
                  int D, int tiles_per_mol)
{
    extern __shared__ __align__(16) float s_ns[];

    const int m    = blockIdx.x / tiles_per_mol;
    const int tile = blockIdx.x - m * tiles_per_mol;
    const int row0 = tile * ROWS_PER_BLOCK;

    const float* nsm = ns + (size_t)m * D;
    const int nch = D >> 2;
    for (int i = threadIdx.x; i < nch; i += BLOCK_THREADS)
        ((float4*)s_ns)[i] = ((const float4*)nsm)[i];
    for (int i = nch * 4 + threadIdx.x; i < D; i += BLOCK_THREADS)
        s_ns[i] = nsm[i];
    __syncthreads();

    const int warp  = threadIdx.x >> 5;
    const int lane  = threadIdx.x & 31;
    const int nwrps = BLOCK_THREADS >> 5;

    const float4* s4    = (const float4*)s_ns;
    const float*  hbase = hess + (size_t)m * D * D;

    int rend = row0 + ROWS_PER_BLOCK;
    if (rend > D) rend = D;

    for (int r = row0 + warp; r < rend; r += nwrps) {
        const float4* hrow = (const float4*)(hbase + (size_t)r * D);
        float acc = 0.0f;
        for (int c = lane; c < nch; c += 32) {
            const float4 h = __ldcs(hrow + c);
            const float4 n = s4[c];
            acc = fmaf(h.x, n.x, acc);
            acc = fmaf(h.y, n.y, acc);
            acc = fmaf(h.z, n.z, acc);
            acc = fmaf(h.w, n.w, acc);
        }
        for (int c = nch * 4 + lane; c < D; c += 32)
            acc = fmaf(hbase[(size_t)r * D + c], s_ns[c], acc);
#pragma unroll
        for (int off = 16; off; off >>= 1)
            acc += __shfl_xor_sync(0xffffffffu, acc, off);
        if (lane == 0)
            out[(size_t)m * D + r] = acc;
    }
}

extern "C" void kernel_launch(void* const* d_in, const int* in_sizes, int n_in,
                              void* d_out, int out_size)
{
    // Input order: ns [M*N_AT,3] f32, hess [M*D,D] f32, idx_m i32, n_atoms [M] i32
    const float* ns   = (const float*)d_in[0];
    const float* hess = (const float*)d_in[1];
    float*       out  = (float*)d_out;

    const int M = in_sizes[3];
    const int D = (int)((long long)in_sizes[0] / M);

    const int tiles = (D + ROWS_PER_BLOCK - 1) / ROWS_PER_BLOCK;
    const dim3 grid((unsigned)(M * tiles));
    const dim3 block(BLOCK_THREADS);

    if (D == 300) {
        force_agg_300<<<grid, block>>>(hess, ns, out, tiles);
    } else {
        const size_t shmem = (size_t)((D + 3) / 4) * 16;
        force_agg_generic<<<grid, block, shmem>>>(hess, ns, out, D, tiles);
    }
}